// round 16
// baseline (speedup 1.0000x reference)
#include <cuda_runtime.h>
#include <math.h>

// Inputs (metadata order):
//   d_in[0]: z          float32, n_nodes*512   (n_nodes = 50000)
//   d_in[1]: edge_index int32,   2*n_edges     (n_edges = 150000)
// Output: float32, 150000

#define D 512
#define ROW_U4 (D / 16)        // 32 uint4 per int8 row (512 bytes)
#define MAX_NODES 50000
#define MAX_EDGES 150000
#define CAP 24                 // max slots per source node (Poisson(3) tail ~0)
#define EPS 1e-6f

// Scratch (static device arrays; no allocation in kernel_launch):
__device__ uint4  g_q[(size_t)MAX_NODES * ROW_U4];   // 25.6 MB quantized normalized rows
__device__ float2 g_ss[MAX_NODES];                   // {quant step, normalized sum}
__device__ int    g_cnt[MAX_NODES];                  // per-source degree
__device__ int2   g_slots[(size_t)MAX_NODES * CAP];  // (ib, e) per source
__device__ int    g_ovf_n;                           // overflow count
__device__ int4   g_ovf[MAX_EDGES];                  // (ia, ib, e, 0) overflow edges

__device__ __forceinline__ unsigned pack4(float x, float y, float z, float w, float k) {
    int q0 = __float2int_rn(x * k);
    int q1 = __float2int_rn(y * k);
    int q2 = __float2int_rn(z * k);
    int q3 = __float2int_rn(w * k);
    q0 = max(-127, min(127, q0));
    q1 = max(-127, min(127, q1));
    q2 = max(-127, min(127, q2));
    q3 = max(-127, min(127, q3));
    return (unsigned)(q0 & 0xFF) | ((unsigned)(q1 & 0xFF) << 8) |
           ((unsigned)(q2 & 0xFF) << 16) | ((unsigned)(q3 & 0xFF) << 24);
}

__device__ __forceinline__ void cp_async16(void* smem_dst, const void* gsrc) {
    unsigned saddr = (unsigned)__cvta_generic_to_shared(smem_dst);
    asm volatile("cp.async.cg.shared.global [%0], [%1], 16;\n" :: "r"(saddr), "l"(gsrc));
}

__device__ __forceinline__ float edge_result(float idot, float2 ssa, float2 ssb) {
    float dot = idot * ssa.x * ssb.x;
    float d2 = 2.0f - 2.0f * dot
             + 2.0f * EPS * (ssa.y - ssb.y)
             + (float)D * EPS * EPS;
    d2 = fmaxf(d2, 0.0f);
    float v = 1.0f - sqrtf(d2);
    return 1.0f / (1.0f + expf(-v));
}

// ---------------------------------------------------------------------------
// K0: zero counters.
// ---------------------------------------------------------------------------
__global__ void zero_kernel(int n_nodes) {
    int i = blockIdx.x * blockDim.x + threadIdx.x;
    if (i == 0) g_ovf_n = 0;
    for (; i < n_nodes; i += gridDim.x * blockDim.x) g_cnt[i] = 0;
}

// ---------------------------------------------------------------------------
// K1: normalize rows (blocks [0, nb_rows)) + bin edges by source
//     (blocks [nb_rows, nb_rows + nb_bin)). Normalize is DRAM-bound; binning
//     rides along nearly free.
// ---------------------------------------------------------------------------
__global__ void normalize_bin_kernel(const float* __restrict__ z,
                                     const int* __restrict__ ei,
                                     int n_nodes, int n_edges, int nb_rows) {
    if ((int)blockIdx.x >= nb_rows) {
        // ---- binning part ----
        int bidx = blockIdx.x - nb_rows;
        int tid = bidx * blockDim.x + threadIdx.x;
        int stride = (gridDim.x - nb_rows) * blockDim.x;
        for (int e = tid; e < n_edges; e += stride) {
            int ia = __ldg(ei + e);
            int ib = __ldg(ei + n_edges + e);
            int pos = atomicAdd(&g_cnt[ia], 1);
            if (pos < CAP) {
                g_slots[(size_t)ia * CAP + pos] = make_int2(ib, e);
            } else {
                int o = atomicAdd(&g_ovf_n, 1);
                g_ovf[o] = make_int4(ia, ib, e, 0);
            }
        }
        return;
    }

    // ---- normalize part: one warp per row ----
    int row  = (blockIdx.x * blockDim.x + threadIdx.x) >> 5;
    int lane = threadIdx.x & 31;
    if (row >= n_nodes) return;

    const float4* __restrict__ Z = (const float4*)(z + (size_t)row * D);
    float4 v[4];
    float n2 = 0.f, s = 0.f, mx = 0.f;
#pragma unroll
    for (int j = 0; j < 4; j++) {
        v[j] = __ldcs(Z + lane + 32 * j);   // evict-first: keep table in L2
        n2 += v[j].x * v[j].x + v[j].y * v[j].y + v[j].z * v[j].z + v[j].w * v[j].w;
        s  += v[j].x + v[j].y + v[j].z + v[j].w;
        mx = fmaxf(mx, fmaxf(fmaxf(fabsf(v[j].x), fabsf(v[j].y)),
                             fmaxf(fabsf(v[j].z), fabsf(v[j].w))));
    }
#pragma unroll
    for (int off = 16; off > 0; off >>= 1) {
        n2 += __shfl_xor_sync(0xFFFFFFFFu, n2, off);
        s  += __shfl_xor_sync(0xFFFFFFFFu, s,  off);
        mx = fmaxf(mx, __shfl_xor_sync(0xFFFFFFFFu, mx, off));
    }

    float inv = rsqrtf(n2);
    float step = mx * inv * (1.0f / 127.0f);
    float qk = 127.0f / mx;

    if (lane == 0) g_ss[row] = make_float2(step, s * inv);

    uint4 u;
    u.x = pack4(v[0].x, v[0].y, v[0].z, v[0].w, qk);
    u.y = pack4(v[1].x, v[1].y, v[1].z, v[1].w, qk);
    u.z = pack4(v[2].x, v[2].y, v[2].z, v[2].w, qk);
    u.w = pack4(v[3].x, v[3].y, v[3].z, v[3].w, qk);
    g_q[(size_t)row * ROW_U4 + lane] = u;
}

// ---------------------------------------------------------------------------
// K2: source-grouped edge kernel. 8 lanes per node; A row read ONCE into
// registers; B rows double-buffered via cp.async; dp4a + REDUX; scatter out.
// SMEM: 8 warps x 4 subs x 2 stages x 512B = 32KB/block.
// ---------------------------------------------------------------------------
__global__ void __launch_bounds__(256)
edge_group_kernel(float* __restrict__ out, int n_nodes, int n_edges) {
    __shared__ __align__(16) uint4 sbuf[8][4][2][32];

    int wib  = threadIdx.x >> 5;
    int lane = threadIdx.x & 31;
    int sub  = lane >> 3;       // node-group within warp (0..3)
    int sl   = lane & 7;        // lane within group
    unsigned gmask = 0xFFu << (sub * 8);

    int grp = (blockIdx.x * 8 + wib) * 4 + sub;
    int G   = gridDim.x * 32;   // total groups

    for (int n = grp; n < n_nodes; n += G) {
        int deg = g_cnt[n];
        int degm = min(deg, CAP);
        if (degm == 0) continue;

        const int2* sl_ptr = g_slots + (size_t)n * CAP;
        int2 s0 = __ldg(sl_ptr);

        // issue B row of edge 0 (stage 0), then overlap the A-row load
        {
            const uint4* B = g_q + (size_t)s0.x * ROW_U4;
            uint4* dst = &sbuf[wib][sub][0][0];
#pragma unroll
            for (int j = 0; j < 4; j++)
                cp_async16(&dst[sl + 8 * j], &B[sl + 8 * j]);
        }
        asm volatile("cp.async.commit_group;\n" ::: "memory");

        // A row into registers (hits L2 under the cp.async latency)
        uint4 a[4];
        const uint4* A = g_q + (size_t)n * ROW_U4;
#pragma unroll
        for (int j = 0; j < 4; j++) a[j] = __ldg(&A[sl + 8 * j]);
        float2 ssa = g_ss[n];

        for (int j = 0; j < degm; j++) {
            bool hn = (j + 1) < degm;
            int2 s1 = s0;
            if (hn) {
                s1 = __ldg(sl_ptr + j + 1);
                const uint4* B = g_q + (size_t)s1.x * ROW_U4;
                uint4* dst = &sbuf[wib][sub][(j + 1) & 1][0];
#pragma unroll
                for (int k = 0; k < 4; k++)
                    cp_async16(&dst[sl + 8 * k], &B[sl + 8 * k]);
            }
            asm volatile("cp.async.commit_group;\n" ::: "memory");

            float2 ssb = g_ss[s0.x];

            if (hn) asm volatile("cp.async.wait_group 1;\n" ::: "memory");
            else    asm volatile("cp.async.wait_group 0;\n" ::: "memory");

            const uint4* sB = &sbuf[wib][sub][j & 1][0];
            int idot = 0;
#pragma unroll
            for (int k = 0; k < 4; k++) {
                uint4 b = sB[sl + 8 * k];
                idot = __dp4a((int)a[k].x, (int)b.x, idot);
                idot = __dp4a((int)a[k].y, (int)b.y, idot);
                idot = __dp4a((int)a[k].z, (int)b.z, idot);
                idot = __dp4a((int)a[k].w, (int)b.w, idot);
            }
            idot = __reduce_add_sync(gmask, idot);

            if (sl == 0) out[s0.y] = edge_result((float)idot, ssa, ssb);
            s0 = s1;
        }
    }

    // ---- overflow slow path (expected empty; required for correctness) ----
    int no = g_ovf_n;
    for (int k = grp; k < no; k += G) {
        int4 t = g_ovf[k];
        const uint4* A = g_q + (size_t)t.x * ROW_U4;
        const uint4* B = g_q + (size_t)t.y * ROW_U4;
        int idot = 0;
#pragma unroll
        for (int j = 0; j < 4; j++) {
            uint4 av = __ldg(&A[sl + 8 * j]);
            uint4 bv = __ldg(&B[sl + 8 * j]);
            idot = __dp4a((int)av.x, (int)bv.x, idot);
            idot = __dp4a((int)av.y, (int)bv.y, idot);
            idot = __dp4a((int)av.z, (int)bv.z, idot);
            idot = __dp4a((int)av.w, (int)bv.w, idot);
        }
        idot = __reduce_add_sync(gmask, idot);
        if (sl == 0) out[t.z] = edge_result((float)idot, g_ss[t.x], g_ss[t.y]);
    }
}

extern "C" void kernel_launch(void* const* d_in, const int* in_sizes, int n_in,
                              void* d_out, int out_size) {
    const float* z = (const float*)d_in[0];
    const int* ei  = (const int*)d_in[1];
    float* out     = (float*)d_out;

    int n_nodes = in_sizes[0] / D;   // 50000
    int n_edges = out_size;          // 150000

    zero_kernel<<<64, 256>>>(n_nodes);

    int nb_rows = (n_nodes + 7) / 8;   // 8 rows per 256-thread block
    int nb_bin  = 148;
    normalize_bin_kernel<<<nb_rows + nb_bin, 256>>>(z, ei, n_nodes, n_edges, nb_rows);

    edge_group_kernel<<<148 * 5, 256>>>(out, n_nodes, n_edges);
}